// round 15
// baseline (speedup 1.0000x reference)
#include <cuda_runtime.h>
#include <cuda_bf16.h>

// Shapes (compile-time constants)
#define NB   512           // sequence length
#define DD   256           // model dim
#define HH   8             // heads
#define HID  682           // swiglu hidden
#define QKVD 768

typedef unsigned long long u64;

// ---------------- device scratch ----------------
__device__ float g_xn[NB * DD];
__device__ float g_qkv[NB * QKVD];
__device__ float2 g_PKT[DD * NB];    // (.x = K^T[k][j], .y = 0.5*Pb^T[k][j])
__device__ float g_Pb[NB * DD];      // 0.5 * Pb
__device__ float g_Pv[NB * DD];      // 0.5 * Pv
__device__ float g_rv2T[DD * DD];    // rv2 transposed [k][d]
__device__ float g_w[NB * NB * HH];  // logit partial kh=0 -> final softmax weights (8MB)
__device__ float g_w2[NB * NB * HH]; // logit partial kh=1 (8MB)
__device__ float g_Tp[512 * 4 * HH * DD];  // partial T: [(g*4+jp)*4+q][h*DD+k] (16MB)
__device__ float g_c1p[512 * 4 * DD];      // partial c1 (2MB)
__device__ float g_y[NB * DD];
__device__ float g_xn2[NB * DD];
__device__ float g_h1[NB * HID];

// ---- packed f32x2 helpers (sm_100+) ----
__device__ __forceinline__ u64 pk2(float lo, float hi) {
    u64 r;
    asm("mov.b64 %0, {%1, %2};" : "=l"(r) : "f"(lo), "f"(hi));
    return r;
}
__device__ __forceinline__ float2 up2(u64 v) {
    float2 f;
    asm("mov.b64 {%0, %1}, %2;" : "=f"(f.x), "=f"(f.y) : "l"(v));
    return f;
}
__device__ __forceinline__ u64 fma2(u64 a, u64 b, u64 c) {
    u64 d;
    asm("fma.rn.f32x2 %0, %1, %2, %3;" : "=l"(d) : "l"(a), "l"(b), "l"(c));
    return d;
}
__device__ __forceinline__ u64 add2(u64 a, u64 b) {
    u64 d;
    asm("add.rn.f32x2 %0, %1, %2;" : "=l"(d) : "l"(a), "l"(b));
    return d;
}

// silu from the HALF-difference s = 0.5*(a-b): silu(a-b) = s*tanh(s)+s
__device__ __forceinline__ float silu_h(float s) {
    float t;
    asm("tanh.approx.f32 %0, %1;" : "=f"(t) : "f"(s));
    return fmaf(s, t, s);
}
// accurate silu for the (cold) FFN epilogue
__device__ __forceinline__ float silu_acc(float v) {
    return v / (1.0f + __expf(-v));
}

// ---------------- LayerNorm: one block per row, 256 threads ----------------
__global__ __launch_bounds__(256) void ln_kernel(const float* __restrict__ x,
                                                 const float* __restrict__ w,
                                                 const float* __restrict__ b,
                                                 float* __restrict__ out) {
    int row = blockIdx.x, t = threadIdx.x;
    float v = x[row * DD + t];
    float s = v, q = v * v;
#pragma unroll
    for (int o = 16; o; o >>= 1) {
        s += __shfl_xor_sync(0xffffffff, s, o);
        q += __shfl_xor_sync(0xffffffff, q, o);
    }
    __shared__ float ss[8], sq[8];
    int warp = t >> 5, lane = t & 31;
    if (lane == 0) { ss[warp] = s; sq[warp] = q; }
    __syncthreads();
    s = 0.f; q = 0.f;
#pragma unroll
    for (int k = 0; k < 8; k++) { s += ss[k]; q += sq[k]; }
    float mean = s * (1.0f / DD);
    float var = q * (1.0f / DD) - mean * mean;
    out[row * DD + t] = (v - mean) * rsqrtf(var + 1e-5f) * w[t] + b[t];
}

// ---------------- coords projection (all outputs HALF-scaled) ----------------
__global__ __launch_bounds__(256) void proj3_kernel(const float* __restrict__ coords,
                                                    const float* __restrict__ rb1,
                                                    const float* __restrict__ rv1,
                                                    float* __restrict__ Pb,
                                                    float2* __restrict__ PKT,
                                                    float* __restrict__ Pv) {
    int i = blockIdx.x, k = threadIdx.x;
    float c0 = coords[i * 3 + 0], c1 = coords[i * 3 + 1], c2 = coords[i * 3 + 2];
    float pb = rb1[k * 3 + 0] * c0 + rb1[k * 3 + 1] * c1 + rb1[k * 3 + 2] * c2;
    float pv = rv1[k * 3 + 0] * c0 + rv1[k * 3 + 1] * c1 + rv1[k * 3 + 2] * c2;
    Pb[i * DD + k] = 0.5f * pb;
    PKT[k * NB + i].y = 0.5f * pb;
    Pv[i * DD + k] = 0.5f * pv;
}

// ---------------- generic 32x32-tiled transpose ----------------
__global__ __launch_bounds__(256) void transpose_kernel(const float* __restrict__ in,
                                                        float* __restrict__ out,
                                                        int R, int C, int ldin, int off) {
    __shared__ float tile[32][33];
    int c0 = blockIdx.x * 32, r0 = blockIdx.y * 32;
    int tx = threadIdx.x, ty = threadIdx.y;  // 32 x 8
#pragma unroll
    for (int s = 0; s < 32; s += 8)
        tile[ty + s][tx] = in[(r0 + ty + s) * ldin + off + c0 + tx];
    __syncthreads();
#pragma unroll
    for (int s = 0; s < 32; s += 8)
        out[(c0 + ty + s) * R + r0 + tx] = tile[tx][ty + s];
}

// ---------------- GEMM: C = A @ W^T (+bias), 32x64 tile; optional K^T side-write ----
__global__ __launch_bounds__(256, 2) void gemm_t(const float* __restrict__ A,
                                                 const float* __restrict__ W,
                                                 const float* __restrict__ bias,
                                                 float2* __restrict__ PKT,  // nullable
                                                 float* __restrict__ C,
                                                 int M, int N, int K) {
    __shared__ __align__(16) u64 As[32][34];     // [k][m] duplicated
    __shared__ __align__(16) float Ws[32][68];   // [k][n]
    int tid = threadIdx.x;
    int tx = tid & 15, ty = tid >> 4;            // tx -> n (4 cols), ty -> m (2 rows)
    int row0 = blockIdx.y * 32, col0 = blockIdx.x * 64;
    u64 acc[2][2] = {};
    for (int k0 = 0; k0 < K; k0 += 32) {
#pragma unroll
        for (int l = 0; l < 4; l++) {            // A: 32x32
            int idx = l * 256 + tid;
            int m = idx >> 5, k = idx & 31;
            int gk = k0 + k, ar = row0 + m;
            float v = (ar < M && gk < K) ? A[ar * K + gk] : 0.f;
            As[k][m] = pk2(v, v);
        }
#pragma unroll
        for (int l = 0; l < 8; l++) {            // W: 64x32
            int idx = l * 256 + tid;
            int m = idx >> 5, k = idx & 31;
            int gk = k0 + k, wr = col0 + m;
            Ws[k][m] = (wr < N && gk < K) ? W[wr * K + gk] : 0.f;
        }
        __syncthreads();
#pragma unroll
        for (int kk = 0; kk < 32; kk++) {
            ulonglong2 Av = *(const ulonglong2*)&As[kk][ty * 2];
            ulonglong2 Bv = *(const ulonglong2*)&Ws[kk][tx * 4];
            acc[0][0] = fma2(Av.x, Bv.x, acc[0][0]);
            acc[0][1] = fma2(Av.x, Bv.y, acc[0][1]);
            acc[1][0] = fma2(Av.y, Bv.x, acc[1][0]);
            acc[1][1] = fma2(Av.y, Bv.y, acc[1][1]);
        }
        __syncthreads();
    }
#pragma unroll
    for (int r = 0; r < 2; r++) {
        int m = row0 + ty * 2 + r;
        if (m >= M) continue;
#pragma unroll
        for (int c2 = 0; c2 < 2; c2++) {
            float2 v = up2(acc[r][c2]);
            int n0 = col0 + tx * 4 + c2 * 2;
            if (n0 < N) {
                float o = v.x + (bias ? bias[n0] : 0.f);
                C[m * N + n0] = o;
                if (PKT && n0 >= DD && n0 < 2 * DD) PKT[(n0 - DD) * NB + m].x = o;
            }
            if (n0 + 1 < N) {
                float o = v.y + (bias ? bias[n0 + 1] : 0.f);
                C[m * N + n0 + 1] = o;
                if (PKT && n0 + 1 >= DD && n0 + 1 < 2 * DD) PKT[(n0 + 1 - DD) * NB + m].x = o;
            }
        }
    }
}

// ---------------- GEMM 32x32 tile (better grid fill for small N) ----------------
__global__ __launch_bounds__(256, 3) void gemm_t32(const float* __restrict__ A,
                                                   const float* __restrict__ W,
                                                   const float* __restrict__ bias,
                                                   const float* __restrict__ residual,
                                                   float* __restrict__ C,
                                                   int M, int N, int K) {
    __shared__ __align__(16) u64 As[32][34];     // [k][m] duplicated
    __shared__ __align__(16) float Ws[32][36];   // [k][n]
    int tid = threadIdx.x;
    int tx = tid & 7, ty = tid >> 3;             // tx -> n (4 cols), ty -> m (1 row)
    int row0 = blockIdx.y * 32, col0 = blockIdx.x * 32;
    u64 acc[2] = {};
    for (int k0 = 0; k0 < K; k0 += 32) {
#pragma unroll
        for (int l = 0; l < 4; l++) {
            int idx = l * 256 + tid;
            int m = idx >> 5, k = idx & 31;
            int gk = k0 + k;
            int ar = row0 + m, wr = col0 + m;
            float va = (ar < M && gk < K) ? A[ar * K + gk] : 0.f;
            As[k][m] = pk2(va, va);
            Ws[k][m] = (wr < N && gk < K) ? W[wr * K + gk] : 0.f;
        }
        __syncthreads();
#pragma unroll
        for (int kk = 0; kk < 32; kk++) {
            u64 Av = As[kk][ty];
            ulonglong2 Bv = *(const ulonglong2*)&Ws[kk][tx * 4];
            acc[0] = fma2(Av, Bv.x, acc[0]);
            acc[1] = fma2(Av, Bv.y, acc[1]);
        }
        __syncthreads();
    }
    int m = row0 + ty;
    if (m < M) {
#pragma unroll
        for (int c2 = 0; c2 < 2; c2++) {
            float2 v = up2(acc[c2]);
            int n0 = col0 + tx * 4 + c2 * 2;
            if (n0 < N) {
                float o = v.x;
                if (bias) o += bias[n0];
                if (residual) o += residual[m * N + n0];
                C[m * N + n0] = o;
            }
            if (n0 + 1 < N) {
                float o = v.y;
                if (bias) o += bias[n0 + 1];
                if (residual) o += residual[m * N + n0 + 1];
                C[m * N + n0 + 1] = o;
            }
        }
    }
}

// ---------------- fused SwiGLU dual-GEMM, 32x64 tile ----------------
__global__ __launch_bounds__(256, 2) void gemm_swiglu(const float* __restrict__ A,
                                                      const float* __restrict__ W1,
                                                      const float* __restrict__ b1,
                                                      const float* __restrict__ W2,
                                                      const float* __restrict__ b2,
                                                      float* __restrict__ Hout,
                                                      int M, int N, int K) {
    __shared__ __align__(16) u64 As[32][34];
    __shared__ __align__(16) float W1s[32][68];
    __shared__ __align__(16) float W2s[32][68];
    int tid = threadIdx.x;
    int tx = tid & 15, ty = tid >> 4;
    int row0 = blockIdx.y * 32, col0 = blockIdx.x * 64;
    u64 acc1[2][2] = {};
    u64 acc2[2][2] = {};
    for (int k0 = 0; k0 < K; k0 += 32) {
#pragma unroll
        for (int l = 0; l < 4; l++) {
            int idx = l * 256 + tid;
            int m = idx >> 5, k = idx & 31;
            int gk = k0 + k, ar = row0 + m;
            float v = (ar < M && gk < K) ? A[ar * K + gk] : 0.f;
            As[k][m] = pk2(v, v);
        }
#pragma unroll
        for (int l = 0; l < 8; l++) {
            int idx = l * 256 + tid;
            int m = idx >> 5, k = idx & 31;
            int gk = k0 + k, wr = col0 + m;
            W1s[k][m] = (wr < N && gk < K) ? W1[wr * K + gk] : 0.f;
            W2s[k][m] = (wr < N && gk < K) ? W2[wr * K + gk] : 0.f;
        }
        __syncthreads();
#pragma unroll
        for (int kk = 0; kk < 32; kk++) {
            ulonglong2 Av = *(const ulonglong2*)&As[kk][ty * 2];
            ulonglong2 Bv = *(const ulonglong2*)&W1s[kk][tx * 4];
            ulonglong2 Cv = *(const ulonglong2*)&W2s[kk][tx * 4];
            acc1[0][0] = fma2(Av.x, Bv.x, acc1[0][0]);
            acc1[0][1] = fma2(Av.x, Bv.y, acc1[0][1]);
            acc1[1][0] = fma2(Av.y, Bv.x, acc1[1][0]);
            acc1[1][1] = fma2(Av.y, Bv.y, acc1[1][1]);
            acc2[0][0] = fma2(Av.x, Cv.x, acc2[0][0]);
            acc2[0][1] = fma2(Av.x, Cv.y, acc2[0][1]);
            acc2[1][0] = fma2(Av.y, Cv.x, acc2[1][0]);
            acc2[1][1] = fma2(Av.y, Cv.y, acc2[1][1]);
        }
        __syncthreads();
    }
#pragma unroll
    for (int r = 0; r < 2; r++) {
        int m = row0 + ty * 2 + r;
        if (m >= M) continue;
#pragma unroll
        for (int c2 = 0; c2 < 2; c2++) {
            float2 v1 = up2(acc1[r][c2]);
            float2 v2 = up2(acc2[r][c2]);
            int n0 = col0 + tx * 4 + c2 * 2;
            if (n0 < N)
                Hout[m * N + n0] = silu_acc(v1.x + b1[n0]) * (v2.x + b2[n0]);
            if (n0 + 1 < N)
                Hout[m * N + n0 + 1] = silu_acc(v1.y + b1[n0 + 1]) * (v2.y + b2[n0 + 1]);
        }
    }
}

// ---------------- attention 1a: partial logits, 4 queries per block -----------------
// grid (128 groups, 2 j-halves, 2 k-halves), 256 threads; thread owns one j, 4 queries.
__global__ __launch_bounds__(256, 3) void attn_logits(
    const float* __restrict__ qkv, const float2* __restrict__ PKT,
    const float* __restrict__ Pb, const float* __restrict__ rb1_b,
    const float* __restrict__ rb2_w, const float* __restrict__ rb2_b,
    float* __restrict__ gw_p0, float* __restrict__ gw_p1) {
    const int i0 = blockIdx.x * 4;
    const int j = blockIdx.y * 256 + threadIdx.x;
    const int kh = blockIdx.z;
    const int kbase = kh * 128;
    const int t = threadIdx.x;

    __shared__ __align__(16) float4 sm_q[128];        // q for 4 queries, k-half
    __shared__ __align__(16) float4 sm_hpb[128];      // 0.5*Pbq for 4 queries
    __shared__ __align__(16) float sm_rb2[128 * HH];  // rb2 transposed [k'][h]

    if (t < 128) {
        int k = kbase + t;
        float hb = 0.5f * rb1_b[k];
        sm_q[t] = make_float4(qkv[(i0 + 0) * QKVD + k], qkv[(i0 + 1) * QKVD + k],
                              qkv[(i0 + 2) * QKVD + k], qkv[(i0 + 3) * QKVD + k]);
        sm_hpb[t] = make_float4(Pb[(i0 + 0) * DD + k] + hb, Pb[(i0 + 1) * DD + k] + hb,
                                Pb[(i0 + 2) * DD + k] + hb, Pb[(i0 + 3) * DD + k] + hb);
    }
#pragma unroll
    for (int l = 0; l < 4; l++) {
        int idx = l * 256 + t;          // 0..1023
        int h = idx >> 7, kp = idx & 127;
        sm_rb2[kp * HH + h] = rb2_w[h * DD + kbase + kp];
    }
    __syncthreads();

    u64 bias[4][4] = {};   // [q][head pair], partial over this k-half
    const float sc = 0.17677669529663687f;
#pragma unroll
    for (int hq = 0; hq < 4; hq++) {     // global head = kh*4+hq
        float qk0 = 0.f, qk1 = 0.f, qk2 = 0.f, qk3 = 0.f;
#pragma unroll 4
        for (int kk = 0; kk < 32; kk++) {
            int kp = hq * 32 + kk;
            float2 pk = PKT[(kbase + kp) * NB + j];
            ulonglong2 rA = *(const ulonglong2*)(sm_rb2 + kp * HH);
            ulonglong2 rB = *(const ulonglong2*)(sm_rb2 + kp * HH + 4);
            float4 qv = sm_q[kp];
            float4 hp = sm_hpb[kp];
            qk0 = fmaf(qv.x, pk.x, qk0);
            qk1 = fmaf(qv.y, pk.x, qk1);
            qk2 = fmaf(qv.z, pk.x, qk2);
            qk3 = fmaf(qv.w, pk.x, qk3);
            {
                float u = silu_h(hp.x - pk.y);
                u64 up = pk2(u, u);
                bias[0][0] = fma2(up, rA.x, bias[0][0]);
                bias[0][1] = fma2(up, rA.y, bias[0][1]);
                bias[0][2] = fma2(up, rB.x, bias[0][2]);
                bias[0][3] = fma2(up, rB.y, bias[0][3]);
            }
            {
                float u = silu_h(hp.y - pk.y);
                u64 up = pk2(u, u);
                bias[1][0] = fma2(up, rA.x, bias[1][0]);
                bias[1][1] = fma2(up, rA.y, bias[1][1]);
                bias[1][2] = fma2(up, rB.x, bias[1][2]);
                bias[1][3] = fma2(up, rB.y, bias[1][3]);
            }
            {
                float u = silu_h(hp.z - pk.y);
                u64 up = pk2(u, u);
                bias[2][0] = fma2(up, rA.x, bias[2][0]);
                bias[2][1] = fma2(up, rA.y, bias[2][1]);
                bias[2][2] = fma2(up, rB.x, bias[2][2]);
                bias[2][3] = fma2(up, rB.y, bias[2][3]);
            }
            {
                float u = silu_h(hp.w - pk.y);
                u64 up = pk2(u, u);
                bias[3][0] = fma2(up, rA.x, bias[3][0]);
                bias[3][1] = fma2(up, rA.y, bias[3][1]);
                bias[3][2] = fma2(up, rB.x, bias[3][2]);
                bias[3][3] = fma2(up, rB.y, bias[3][3]);
            }
        }
        int hg = kh * 4 + hq;
        int c = hg >> 1;
        float qks[4] = {qk0 * sc, qk1 * sc, qk2 * sc, qk3 * sc};
#pragma unroll
        for (int q = 0; q < 4; q++) {
            u64 p = (hg & 1) ? pk2(0.f, qks[q]) : pk2(qks[q], 0.f);
            bias[q][c] = add2(bias[q][c], p);
        }
    }
    // write partial logits (rb2_b folded into kh=0 partial only)
    float* gw_part = kh ? gw_p1 : gw_p0;
#pragma unroll
    for (int q = 0; q < 4; q++) {
        u64* wq = (u64*)(gw_part + (i0 + q) * NB * HH + j * HH);
        if (kh == 0) {
#pragma unroll
            for (int c = 0; c < 4; c++) {
                u64 bb = pk2(rb2_b[2 * c], rb2_b[2 * c + 1]);
                wq[c] = add2(bias[q][c], bb);
            }
        } else {
#pragma unroll
            for (int c = 0; c < 4; c++) wq[c] = bias[q][c];
        }
    }
}

// ---------------- attention 1b: combine partials + softmax -> gw_p0 -----------------
__global__ __launch_bounds__(256, 4) void softmax_kernel(float* __restrict__ gw_all,
                                                         const float* __restrict__ gw_b) {
    const int i = blockIdx.x;
    const int t = threadIdx.x;
    __shared__ float sw[NB * 9];   // padded [j][9] for conflict-free per-head access

    float4* gw4 = (float4*)(gw_all + i * NB * HH);
    const float4* gwb4 = (const float4*)(gw_b + i * NB * HH);
#pragma unroll
    for (int l = 0; l < 4; l++) {
        int idx = l * 256 + t;              // 1024 float4
        float4 v = gw4[idx];
        float4 vb = gwb4[idx];
        v.x += vb.x; v.y += vb.y; v.z += vb.z; v.w += vb.w;
        int jj = idx >> 1, half = (idx & 1) * 4;
        sw[jj * 9 + half + 0] = v.x;
        sw[jj * 9 + half + 1] = v.y;
        sw[jj * 9 + half + 2] = v.z;
        sw[jj * 9 + half + 3] = v.w;
    }
    __syncthreads();
    {
        int h = t >> 5, lane = t & 31;
        float m = -1e30f;
        for (int jj = lane; jj < NB; jj += 32) m = fmaxf(m, sw[jj * 9 + h]);
#pragma unroll
        for (int o = 16; o; o >>= 1) m = fmaxf(m, __shfl_xor_sync(0xffffffff, m, o));
        float s = 0.f;
        for (int jj = lane; jj < NB; jj += 32) {
            float e = __expf(sw[jj * 9 + h] - m);
            sw[jj * 9 + h] = e;
            s += e;
        }
#pragma unroll
        for (int o = 16; o; o >>= 1) s += __shfl_xor_sync(0xffffffff, s, o);
        float inv = 1.0f / s;
        for (int jj = lane; jj < NB; jj += 32) sw[jj * 9 + h] *= inv;
    }
    __syncthreads();
#pragma unroll
    for (int l = 0; l < 4; l++) {
        int idx = l * 256 + t;
        int jj = idx >> 1, half = (idx & 1) * 4;
        float4 v;
        v.x = sw[jj * 9 + half + 0];
        v.y = sw[jj * 9 + half + 1];
        v.z = sw[jj * 9 + half + 2];
        v.w = sw[jj * 9 + half + 3];
        gw4[idx] = v;
    }
}

// ---------------- attention 2a: partial T + c1, 4 queries, j-quarters ----------------
// grid (128 groups, 4 j-quarters), 256 threads; 128 j each.
__global__ __launch_bounds__(256, 3) void attn_ctx(
    const float* __restrict__ qkv, const float* __restrict__ Pv,
    const float* __restrict__ rv1_b, const float* __restrict__ gw_all,
    float* __restrict__ Tp, float* __restrict__ c1p) {
    const int g = blockIdx.x;
    const int jp = blockIdx.y;
    const int i0 = g * 4;
    const int jbase = jp * 128;
    const int t = threadIdx.x;

    __shared__ __align__(16) float sm_gw[4][128 * HH];  // staged weights, 16KB

    // stage softmax weights for this j-quarter (coalesced)
#pragma unroll
    for (int q = 0; q < 4; q++) {
        const float4* src = (const float4*)(gw_all + (i0 + q) * NB * HH + jbase * HH);
        float4* dst = (float4*)sm_gw[q];
        dst[t] = src[t];   // 256 float4 = 128 j * 8 h
    }
    __syncthreads();

    const int h = t >> 5;
    float c1[4] = {};
    float pvq[4];
    {
        float pvb = 0.5f * rv1_b[t];
#pragma unroll
        for (int q = 0; q < 4; q++) pvq[q] = Pv[(i0 + q) * DD + t] + pvb;
    }
    const float* Vp = qkv + 2 * DD + t + jbase * QKVD;
    const float* Pvp = Pv + t + jbase * DD;
    u64 T[4][4] = {};
#pragma unroll 2
    for (int jj = 0; jj < 128; jj++) {
        float pv = Pvp[jj * DD];
        float v = Vp[jj * QKVD];
#pragma unroll
        for (int q = 0; q < 4; q++) {
            float s = silu_h(pvq[q] - pv);
            u64 sp = pk2(s, s);
            const float* gwq = sm_gw[q] + jj * HH;
            ulonglong2 w0 = *(const ulonglong2*)gwq;
            ulonglong2 w1 = *(const ulonglong2*)(gwq + 4);
            T[q][0] = fma2(sp, w0.x, T[q][0]);
            T[q][1] = fma2(sp, w0.y, T[q][1]);
            T[q][2] = fma2(sp, w1.x, T[q][2]);
            T[q][3] = fma2(sp, w1.y, T[q][3]);
            c1[q] = fmaf(gwq[h], v, c1[q]);
        }
    }
    int b = g * 4 + jp;
#pragma unroll
    for (int q = 0; q < 4; q++) {
        float* Tg = Tp + (b * 4 + q) * (HH * DD);
#pragma unroll
        for (int c = 0; c < 4; c++) {
            float2 a = up2(T[q][c]);
            Tg[(2 * c) * DD + t] = a.x;
            Tg[(2 * c + 1) * DD + t] = a.y;
        }
        c1p[(b * 4 + q) * DD + t] = c1[q];
    }
}

// ---------------- attention 2b: combine + context2 + residual + fused LN2 -----------
// grid 128 groups; combines 4 j-quarters x 4 queries.
__global__ __launch_bounds__(256, 3) void attn_fin(
    const float* __restrict__ x, const float* __restrict__ rv2T,
    const float* __restrict__ rv2_b, const float* __restrict__ Tp,
    const float* __restrict__ c1p,
    const float* __restrict__ ln2_w, const float* __restrict__ ln2_b,
    float* __restrict__ y, float* __restrict__ xn2) {
    const int g = blockIdx.x;
    const int i0 = g * 4;
    const int t = threadIdx.x;

    __shared__ __align__(16) float sm_T[4][HH * DD];   // combined T, 32KB
    __shared__ float sred[8][8];

    // combine T quarters (coalesced float4)
#pragma unroll
    for (int q = 0; q < 4; q++) {
        float4* D = (float4*)sm_T[q];
#pragma unroll
        for (int l = 0; l < 2; l++) {
            int idx = l * 256 + t;   // 512 float4
            float4 acc = make_float4(0.f, 0.f, 0.f, 0.f);
#pragma unroll
            for (int jp = 0; jp < 4; jp++) {
                const float4* S = (const float4*)(Tp + ((g * 4 + jp) * 4 + q) * (HH * DD));
                float4 v = S[idx];
                acc.x += v.x; acc.y += v.y; acc.z += v.z; acc.w += v.w;
            }
            D[idx] = acc;
        }
    }
    __syncthreads();

    const int d = t;
    const int h = d >> 5;
    float c1[4] = {};
#pragma unroll
    for (int q = 0; q < 4; q++)
#pragma unroll
        for (int jp = 0; jp < 4; jp++)
            c1[q] += c1p[((g * 4 + jp) * 4 + q) * DD + d];

    float bv = rv2_b[d];
    float c2[4] = {bv, bv, bv, bv};
#pragma unroll 4
    for (int k = 0; k < DD; k++) {
        float rv = rv2T[k * DD + d];
        c2[0] += rv * sm_T[0][h * DD + k];
        c2[1] += rv * sm_T[1][h * DD + k];
        c2[2] += rv * sm_T[2][h * DD + k];
        c2[3] += rv * sm_T[3][h * DD + k];
    }
    float yv[4];
#pragma unroll
    for (int q = 0; q < 4; q++) {
        yv[q] = x[(i0 + q) * DD + d] + c1[q] + c2[q];
        y[(i0 + q) * DD + d] = yv[q];
    }

    // fused LN2 over 4 rows
    float s[4], qq[4];
#pragma unroll
    for (int q = 0; q < 4; q++) { s[q] = yv[q]; qq[q] = yv[q] * yv[q]; }
#pragma unroll
    for (int o = 16; o; o >>= 1)
#pragma unroll
        for (int q = 0; q < 4; q++) {
            s[q] += __shfl_xor_sync(0xffffffff, s[q], o);
            qq[q] += __shfl_xor_sync(0xffffffff, qq[q], o);
        }
    int warp = t >> 5, lane = t & 31;
    if (lane == 0)
#pragma unroll
        for (int q = 0; q < 4; q++) { sred[q][warp] = s[q]; sred[4 + q][warp] = qq[q]; }
    __syncthreads();
#pragma unroll
    for (int q = 0; q < 4; q++) {
        float S = 0.f, Q = 0.f;
#pragma unroll
        for (int k = 0; k < 8; k++) { S += sred[q][k]; Q += sred[4 + q][k]; }
        float m = S * (1.0f / DD);
        float var = Q * (1.0f / DD) - m * m;
        xn2[(i0 + q) * DD + d] = (yv[q] - m) * rsqrtf(var + 1e-5f) * ln2_w[d] + ln2_b[d];
    }
}

// ---------------- host launcher ----------------
extern "C" void kernel_launch(void* const* d_in, const int* in_sizes, int n_in,
                              void* d_out, int out_size) {
    const float* x      = (const float*)d_in[0];
    const float* coords = (const float*)d_in[1];
    const float* ln1_w  = (const float*)d_in[2];
    const float* ln1_b  = (const float*)d_in[3];
    const float* ln2_w  = (const float*)d_in[4];
    const float* ln2_b  = (const float*)d_in[5];
    const float* qkv_w  = (const float*)d_in[6];
    const float* qkv_b  = (const float*)d_in[7];
    const float* rb1_w  = (const float*)d_in[8];
    const float* rb1_b  = (const float*)d_in[9];
    const float* rb2_w  = (const float*)d_in[10];
    const float* rb2_b  = (const float*)d_in[11];
    const float* rv1_w  = (const float*)d_in[12];
    const float* rv1_b  = (const float*)d_in[13];
    const float* rv2_w  = (const float*)d_in[14];
    const float* rv2_b  = (const float*)d_in[15];
    const float* ffn_w1 = (const float*)d_in[16];
    const float* ffn_b1 = (const float*)d_in[17];
    const float* ffn_w2 = (const float*)d_in[18];
    const float* ffn_b2 = (const float*)d_in[19];
    const float* ffn_w3 = (const float*)d_in[20];
    const float* ffn_b3 = (const float*)d_in[21];
    float* out = (float*)d_out;

    float *p_xn, *p_qkv, *p_Pb, *p_Pv, *p_rv2T, *p_w, *p_w2, *p_Tp, *p_c1p, *p_y, *p_xn2, *p_h1;
    float2* p_PKT;
    cudaGetSymbolAddress((void**)&p_xn, g_xn);
    cudaGetSymbolAddress((void**)&p_qkv, g_qkv);
    cudaGetSymbolAddress((void**)&p_PKT, g_PKT);
    cudaGetSymbolAddress((void**)&p_Pb, g_Pb);
    cudaGetSymbolAddress((void**)&p_Pv, g_Pv);
    cudaGetSymbolAddress((void**)&p_rv2T, g_rv2T);
    cudaGetSymbolAddress((void**)&p_w, g_w);
    cudaGetSymbolAddress((void**)&p_w2, g_w2);
    cudaGetSymbolAddress((void**)&p_Tp, g_Tp);
    cudaGetSymbolAddress((void**)&p_c1p, g_c1p);
    cudaGetSymbolAddress((void**)&p_y, g_y);
    cudaGetSymbolAddress((void**)&p_xn2, g_xn2);
    cudaGetSymbolAddress((void**)&p_h1, g_h1);

    dim3 tthr(32, 8);

    // 1. LN1
    ln_kernel<<<NB, 256>>>(x, ln1_w, ln1_b, p_xn);
    // 2. QKV = xn @ qkv_w^T + qkv_b  (+ K^T side-write into PKT.x)
    gemm_t<<<dim3(QKVD / 64, NB / 32), 256>>>(p_xn, qkv_w, qkv_b, p_PKT, p_qkv,
                                              NB, QKVD, DD);
    // 3. coords projections (half-scaled: Pb, PKT.y, Pv)
    proj3_kernel<<<NB, 256>>>(coords, rb1_w, rv1_w, p_Pb, p_PKT, p_Pv);
    // 4. attention 1a: partial logits (4 queries x j-half x k-half, 512 blocks)
    attn_logits<<<dim3(NB / 4, 2, 2), 256>>>(p_qkv, p_PKT, p_Pb, rb1_b, rb2_w,
                                             rb2_b, p_w, p_w2);
    // 5. rv2^T
    transpose_kernel<<<dim3(DD / 32, DD / 32), tthr>>>(rv2_w, p_rv2T, DD, DD, DD, 0);
    // 6. attention 1b: combine partials + softmax in place
    softmax_kernel<<<NB, 256>>>(p_w, p_w2);
    // 7. attention 2a: partial T + c1 (4 queries x j-quarters, 512 blocks)
    attn_ctx<<<dim3(NB / 4, 4), 256>>>(p_qkv, p_Pv, rv1_b, p_w, p_Tp, p_c1p);
    // 8. attention 2b: combine + c2 + residual + fused LN2 (128 blocks)
    attn_fin<<<NB / 4, 256>>>(x, p_rv2T, rv2_b, p_Tp, p_c1p, ln2_w, ln2_b, p_y, p_xn2);
    // 9. fused SwiGLU dual-GEMM
    gemm_swiglu<<<dim3((HID + 63) / 64, NB / 32), 256>>>(p_xn2, ffn_w1, ffn_b1,
                                                         ffn_w2, ffn_b2, p_h1,
                                                         NB, HID, DD);
    // 10. out = h1 @ ffn_w3^T + ffn_b3 + y   (32x32 tiles -> 128 blocks)
    gemm_t32<<<dim3(DD / 32, NB / 32), 256>>>(p_h1, ffn_w3, ffn_b3, p_y, out,
                                              NB, DD, HID);
}

// round 16
// speedup vs baseline: 1.0259x; 1.0259x over previous
#include <cuda_runtime.h>
#include <cuda_bf16.h>

// Shapes (compile-time constants)
#define NB   512           // sequence length
#define DD   256           // model dim
#define HH   8             // heads
#define HID  682           // swiglu hidden
#define QKVD 768

typedef unsigned long long u64;

// ---------------- device scratch ----------------
__device__ float g_xn[NB * DD];
__device__ float g_qkv[NB * QKVD];
__device__ float2 g_PKT[DD * NB];    // (.x = K^T[k][j], .y = 0.5*Pb^T[k][j])
__device__ float g_Pb[NB * DD];      // 0.5 * Pb
__device__ float g_Pv[NB * DD];      // 0.5 * Pv
__device__ float g_rv2T[DD * DD];    // rv2 transposed [k][d]
__device__ float g_w[NB * NB * HH];  // logit partial kh=0 -> final softmax weights (8MB)
__device__ float g_w2[NB * NB * HH]; // logit partial kh=1 (8MB)
__device__ float g_Tp[512 * 4 * HH * DD];  // partial T: [(g*4+jp)*4+q][h*DD+k] (16MB)
__device__ float g_c1p[512 * 4 * DD];      // partial c1 (2MB)
__device__ float g_y[NB * DD];
__device__ float g_xn2[NB * DD];
__device__ float g_h1[NB * HID];

// ---- packed f32x2 helpers (sm_100+) ----
__device__ __forceinline__ u64 pk2(float lo, float hi) {
    u64 r;
    asm("mov.b64 %0, {%1, %2};" : "=l"(r) : "f"(lo), "f"(hi));
    return r;
}
__device__ __forceinline__ float2 up2(u64 v) {
    float2 f;
    asm("mov.b64 {%0, %1}, %2;" : "=f"(f.x), "=f"(f.y) : "l"(v));
    return f;
}
__device__ __forceinline__ u64 fma2(u64 a, u64 b, u64 c) {
    u64 d;
    asm("fma.rn.f32x2 %0, %1, %2, %3;" : "=l"(d) : "l"(a), "l"(b), "l"(c));
    return d;
}
__device__ __forceinline__ u64 add2(u64 a, u64 b) {
    u64 d;
    asm("add.rn.f32x2 %0, %1, %2;" : "=l"(d) : "l"(a), "l"(b));
    return d;
}

// silu from the HALF-difference s = 0.5*(a-b): silu(a-b) = s*tanh(s)+s
__device__ __forceinline__ float silu_h(float s) {
    float t;
    asm("tanh.approx.f32 %0, %1;" : "=f"(t) : "f"(s));
    return fmaf(s, t, s);
}
// accurate silu for the (cold) FFN epilogue
__device__ __forceinline__ float silu_acc(float v) {
    return v / (1.0f + __expf(-v));
}

// ---------------- LayerNorm: one block per row, 256 threads ----------------
__global__ __launch_bounds__(256) void ln_kernel(const float* __restrict__ x,
                                                 const float* __restrict__ w,
                                                 const float* __restrict__ b,
                                                 float* __restrict__ out) {
    int row = blockIdx.x, t = threadIdx.x;
    float v = x[row * DD + t];
    float s = v, q = v * v;
#pragma unroll
    for (int o = 16; o; o >>= 1) {
        s += __shfl_xor_sync(0xffffffff, s, o);
        q += __shfl_xor_sync(0xffffffff, q, o);
    }
    __shared__ float ss[8], sq[8];
    int warp = t >> 5, lane = t & 31;
    if (lane == 0) { ss[warp] = s; sq[warp] = q; }
    __syncthreads();
    s = 0.f; q = 0.f;
#pragma unroll
    for (int k = 0; k < 8; k++) { s += ss[k]; q += sq[k]; }
    float mean = s * (1.0f / DD);
    float var = q * (1.0f / DD) - mean * mean;
    out[row * DD + t] = (v - mean) * rsqrtf(var + 1e-5f) * w[t] + b[t];
}

// ---------------- coords projection (all outputs HALF-scaled) ----------------
__global__ __launch_bounds__(256) void proj3_kernel(const float* __restrict__ coords,
                                                    const float* __restrict__ rb1,
                                                    const float* __restrict__ rv1,
                                                    float* __restrict__ Pb,
                                                    float2* __restrict__ PKT,
                                                    float* __restrict__ Pv) {
    int i = blockIdx.x, k = threadIdx.x;
    float c0 = coords[i * 3 + 0], c1 = coords[i * 3 + 1], c2 = coords[i * 3 + 2];
    float pb = rb1[k * 3 + 0] * c0 + rb1[k * 3 + 1] * c1 + rb1[k * 3 + 2] * c2;
    float pv = rv1[k * 3 + 0] * c0 + rv1[k * 3 + 1] * c1 + rv1[k * 3 + 2] * c2;
    Pb[i * DD + k] = 0.5f * pb;
    PKT[k * NB + i].y = 0.5f * pb;
    Pv[i * DD + k] = 0.5f * pv;
}

// ---------------- generic 32x32-tiled transpose ----------------
__global__ __launch_bounds__(256) void transpose_kernel(const float* __restrict__ in,
                                                        float* __restrict__ out,
                                                        int R, int C, int ldin, int off) {
    __shared__ float tile[32][33];
    int c0 = blockIdx.x * 32, r0 = blockIdx.y * 32;
    int tx = threadIdx.x, ty = threadIdx.y;  // 32 x 8
#pragma unroll
    for (int s = 0; s < 32; s += 8)
        tile[ty + s][tx] = in[(r0 + ty + s) * ldin + off + c0 + tx];
    __syncthreads();
#pragma unroll
    for (int s = 0; s < 32; s += 8)
        out[(c0 + ty + s) * R + r0 + tx] = tile[tx][ty + s];
}

// ---------------- GEMM: C = A @ W^T (+bias), 32x64 tile; optional K^T side-write ----
__global__ __launch_bounds__(256, 2) void gemm_t(const float* __restrict__ A,
                                                 const float* __restrict__ W,
                                                 const float* __restrict__ bias,
                                                 float2* __restrict__ PKT,  // nullable
                                                 float* __restrict__ C,
                                                 int M, int N, int K) {
    __shared__ __align__(16) u64 As[32][34];     // [k][m] duplicated
    __shared__ __align__(16) float Ws[32][68];   // [k][n]
    int tid = threadIdx.x;
    int tx = tid & 15, ty = tid >> 4;            // tx -> n (4 cols), ty -> m (2 rows)
    int row0 = blockIdx.y * 32, col0 = blockIdx.x * 64;
    u64 acc[2][2] = {};
    for (int k0 = 0; k0 < K; k0 += 32) {
#pragma unroll
        for (int l = 0; l < 4; l++) {            // A: 32x32
            int idx = l * 256 + tid;
            int m = idx >> 5, k = idx & 31;
            int gk = k0 + k, ar = row0 + m;
            float v = (ar < M && gk < K) ? A[ar * K + gk] : 0.f;
            As[k][m] = pk2(v, v);
        }
#pragma unroll
        for (int l = 0; l < 8; l++) {            // W: 64x32
            int idx = l * 256 + tid;
            int m = idx >> 5, k = idx & 31;
            int gk = k0 + k, wr = col0 + m;
            Ws[k][m] = (wr < N && gk < K) ? W[wr * K + gk] : 0.f;
        }
        __syncthreads();
#pragma unroll
        for (int kk = 0; kk < 32; kk++) {
            ulonglong2 Av = *(const ulonglong2*)&As[kk][ty * 2];
            ulonglong2 Bv = *(const ulonglong2*)&Ws[kk][tx * 4];
            acc[0][0] = fma2(Av.x, Bv.x, acc[0][0]);
            acc[0][1] = fma2(Av.x, Bv.y, acc[0][1]);
            acc[1][0] = fma2(Av.y, Bv.x, acc[1][0]);
            acc[1][1] = fma2(Av.y, Bv.y, acc[1][1]);
        }
        __syncthreads();
    }
#pragma unroll
    for (int r = 0; r < 2; r++) {
        int m = row0 + ty * 2 + r;
        if (m >= M) continue;
#pragma unroll
        for (int c2 = 0; c2 < 2; c2++) {
            float2 v = up2(acc[r][c2]);
            int n0 = col0 + tx * 4 + c2 * 2;
            if (n0 < N) {
                float o = v.x + (bias ? bias[n0] : 0.f);
                C[m * N + n0] = o;
                if (PKT && n0 >= DD && n0 < 2 * DD) PKT[(n0 - DD) * NB + m].x = o;
            }
            if (n0 + 1 < N) {
                float o = v.y + (bias ? bias[n0 + 1] : 0.f);
                C[m * N + n0 + 1] = o;
                if (PKT && n0 + 1 >= DD && n0 + 1 < 2 * DD) PKT[(n0 + 1 - DD) * NB + m].x = o;
            }
        }
    }
}

// ---------------- GEMM 32x32 tile (better grid fill for small N) ----------------
__global__ __launch_bounds__(256, 3) void gemm_t32(const float* __restrict__ A,
                                                   const float* __restrict__ W,
                                                   const float* __restrict__ bias,
                                                   const float* __restrict__ residual,
                                                   float* __restrict__ C,
                                                   int M, int N, int K) {
    __shared__ __align__(16) u64 As[32][34];     // [k][m] duplicated
    __shared__ __align__(16) float Ws[32][36];   // [k][n]
    int tid = threadIdx.x;
    int tx = tid & 7, ty = tid >> 3;             // tx -> n (4 cols), ty -> m (1 row)
    int row0 = blockIdx.y * 32, col0 = blockIdx.x * 32;
    u64 acc[2] = {};
    for (int k0 = 0; k0 < K; k0 += 32) {
#pragma unroll
        for (int l = 0; l < 4; l++) {
            int idx = l * 256 + tid;
            int m = idx >> 5, k = idx & 31;
            int gk = k0 + k;
            int ar = row0 + m, wr = col0 + m;
            float va = (ar < M && gk < K) ? A[ar * K + gk] : 0.f;
            As[k][m] = pk2(va, va);
            Ws[k][m] = (wr < N && gk < K) ? W[wr * K + gk] : 0.f;
        }
        __syncthreads();
#pragma unroll
        for (int kk = 0; kk < 32; kk++) {
            u64 Av = As[kk][ty];
            ulonglong2 Bv = *(const ulonglong2*)&Ws[kk][tx * 4];
            acc[0] = fma2(Av, Bv.x, acc[0]);
            acc[1] = fma2(Av, Bv.y, acc[1]);
        }
        __syncthreads();
    }
    int m = row0 + ty;
    if (m < M) {
#pragma unroll
        for (int c2 = 0; c2 < 2; c2++) {
            float2 v = up2(acc[c2]);
            int n0 = col0 + tx * 4 + c2 * 2;
            if (n0 < N) {
                float o = v.x;
                if (bias) o += bias[n0];
                if (residual) o += residual[m * N + n0];
                C[m * N + n0] = o;
            }
            if (n0 + 1 < N) {
                float o = v.y;
                if (bias) o += bias[n0 + 1];
                if (residual) o += residual[m * N + n0 + 1];
                C[m * N + n0 + 1] = o;
            }
        }
    }
}

// ---------------- fused SwiGLU dual-GEMM, 32x64 tile ----------------
__global__ __launch_bounds__(256, 2) void gemm_swiglu(const float* __restrict__ A,
                                                      const float* __restrict__ W1,
                                                      const float* __restrict__ b1,
                                                      const float* __restrict__ W2,
                                                      const float* __restrict__ b2,
                                                      float* __restrict__ Hout,
                                                      int M, int N, int K) {
    __shared__ __align__(16) u64 As[32][34];
    __shared__ __align__(16) float W1s[32][68];
    __shared__ __align__(16) float W2s[32][68];
    int tid = threadIdx.x;
    int tx = tid & 15, ty = tid >> 4;
    int row0 = blockIdx.y * 32, col0 = blockIdx.x * 64;
    u64 acc1[2][2] = {};
    u64 acc2[2][2] = {};
    for (int k0 = 0; k0 < K; k0 += 32) {
#pragma unroll
        for (int l = 0; l < 4; l++) {
            int idx = l * 256 + tid;
            int m = idx >> 5, k = idx & 31;
            int gk = k0 + k, ar = row0 + m;
            float v = (ar < M && gk < K) ? A[ar * K + gk] : 0.f;
            As[k][m] = pk2(v, v);
        }
#pragma unroll
        for (int l = 0; l < 8; l++) {
            int idx = l * 256 + tid;
            int m = idx >> 5, k = idx & 31;
            int gk = k0 + k, wr = col0 + m;
            W1s[k][m] = (wr < N && gk < K) ? W1[wr * K + gk] : 0.f;
            W2s[k][m] = (wr < N && gk < K) ? W2[wr * K + gk] : 0.f;
        }
        __syncthreads();
#pragma unroll
        for (int kk = 0; kk < 32; kk++) {
            ulonglong2 Av = *(const ulonglong2*)&As[kk][ty * 2];
            ulonglong2 Bv = *(const ulonglong2*)&W1s[kk][tx * 4];
            ulonglong2 Cv = *(const ulonglong2*)&W2s[kk][tx * 4];
            acc1[0][0] = fma2(Av.x, Bv.x, acc1[0][0]);
            acc1[0][1] = fma2(Av.x, Bv.y, acc1[0][1]);
            acc1[1][0] = fma2(Av.y, Bv.x, acc1[1][0]);
            acc1[1][1] = fma2(Av.y, Bv.y, acc1[1][1]);
            acc2[0][0] = fma2(Av.x, Cv.x, acc2[0][0]);
            acc2[0][1] = fma2(Av.x, Cv.y, acc2[0][1]);
            acc2[1][0] = fma2(Av.y, Cv.x, acc2[1][0]);
            acc2[1][1] = fma2(Av.y, Cv.y, acc2[1][1]);
        }
        __syncthreads();
    }
#pragma unroll
    for (int r = 0; r < 2; r++) {
        int m = row0 + ty * 2 + r;
        if (m >= M) continue;
#pragma unroll
        for (int c2 = 0; c2 < 2; c2++) {
            float2 v1 = up2(acc1[r][c2]);
            float2 v2 = up2(acc2[r][c2]);
            int n0 = col0 + tx * 4 + c2 * 2;
            if (n0 < N)
                Hout[m * N + n0] = silu_acc(v1.x + b1[n0]) * (v2.x + b2[n0]);
            if (n0 + 1 < N)
                Hout[m * N + n0 + 1] = silu_acc(v1.y + b1[n0 + 1]) * (v2.y + b2[n0 + 1]);
        }
    }
}

// ---------------- attention 1a: partial logits, 4 queries per block -----------------
// grid (128 groups, 2 j-halves, 2 k-halves), 256 threads; thread owns one j, 4 queries.
__global__ __launch_bounds__(256, 3) void attn_logits(
    const float* __restrict__ qkv, const float2* __restrict__ PKT,
    const float* __restrict__ Pb, const float* __restrict__ rb1_b,
    const float* __restrict__ rb2_w, const float* __restrict__ rb2_b,
    float* __restrict__ gw_p0, float* __restrict__ gw_p1) {
    const int i0 = blockIdx.x * 4;
    const int j = blockIdx.y * 256 + threadIdx.x;
    const int kh = blockIdx.z;
    const int kbase = kh * 128;
    const int t = threadIdx.x;

    __shared__ __align__(16) float4 sm_q[128];        // q for 4 queries, k-half
    __shared__ __align__(16) float4 sm_hpb[128];      // 0.5*Pbq for 4 queries
    __shared__ __align__(16) float sm_rb2[128 * HH];  // rb2 transposed [k'][h]

    if (t < 128) {
        int k = kbase + t;
        float hb = 0.5f * rb1_b[k];
        sm_q[t] = make_float4(qkv[(i0 + 0) * QKVD + k], qkv[(i0 + 1) * QKVD + k],
                              qkv[(i0 + 2) * QKVD + k], qkv[(i0 + 3) * QKVD + k]);
        sm_hpb[t] = make_float4(Pb[(i0 + 0) * DD + k] + hb, Pb[(i0 + 1) * DD + k] + hb,
                                Pb[(i0 + 2) * DD + k] + hb, Pb[(i0 + 3) * DD + k] + hb);
    }
#pragma unroll
    for (int l = 0; l < 4; l++) {
        int idx = l * 256 + t;          // 0..1023
        int h = idx >> 7, kp = idx & 127;
        sm_rb2[kp * HH + h] = rb2_w[h * DD + kbase + kp];
    }
    __syncthreads();

    u64 bias[4][4] = {};   // [q][head pair], partial over this k-half
    const float sc = 0.17677669529663687f;
#pragma unroll
    for (int hq = 0; hq < 4; hq++) {     // global head = kh*4+hq
        float qk0 = 0.f, qk1 = 0.f, qk2 = 0.f, qk3 = 0.f;
#pragma unroll 4
        for (int kk = 0; kk < 32; kk++) {
            int kp = hq * 32 + kk;
            float2 pk = PKT[(kbase + kp) * NB + j];
            ulonglong2 rA = *(const ulonglong2*)(sm_rb2 + kp * HH);
            ulonglong2 rB = *(const ulonglong2*)(sm_rb2 + kp * HH + 4);
            float4 qv = sm_q[kp];
            float4 hp = sm_hpb[kp];
            qk0 = fmaf(qv.x, pk.x, qk0);
            qk1 = fmaf(qv.y, pk.x, qk1);
            qk2 = fmaf(qv.z, pk.x, qk2);
            qk3 = fmaf(qv.w, pk.x, qk3);
            {
                float u = silu_h(hp.x - pk.y);
                u64 up = pk2(u, u);
                bias[0][0] = fma2(up, rA.x, bias[0][0]);
                bias[0][1] = fma2(up, rA.y, bias[0][1]);
                bias[0][2] = fma2(up, rB.x, bias[0][2]);
                bias[0][3] = fma2(up, rB.y, bias[0][3]);
            }
            {
                float u = silu_h(hp.y - pk.y);
                u64 up = pk2(u, u);
                bias[1][0] = fma2(up, rA.x, bias[1][0]);
                bias[1][1] = fma2(up, rA.y, bias[1][1]);
                bias[1][2] = fma2(up, rB.x, bias[1][2]);
                bias[1][3] = fma2(up, rB.y, bias[1][3]);
            }
            {
                float u = silu_h(hp.z - pk.y);
                u64 up = pk2(u, u);
                bias[2][0] = fma2(up, rA.x, bias[2][0]);
                bias[2][1] = fma2(up, rA.y, bias[2][1]);
                bias[2][2] = fma2(up, rB.x, bias[2][2]);
                bias[2][3] = fma2(up, rB.y, bias[2][3]);
            }
            {
                float u = silu_h(hp.w - pk.y);
                u64 up = pk2(u, u);
                bias[3][0] = fma2(up, rA.x, bias[3][0]);
                bias[3][1] = fma2(up, rA.y, bias[3][1]);
                bias[3][2] = fma2(up, rB.x, bias[3][2]);
                bias[3][3] = fma2(up, rB.y, bias[3][3]);
            }
        }
        int hg = kh * 4 + hq;
        int c = hg >> 1;
        float qks[4] = {qk0 * sc, qk1 * sc, qk2 * sc, qk3 * sc};
#pragma unroll
        for (int q = 0; q < 4; q++) {
            u64 p = (hg & 1) ? pk2(0.f, qks[q]) : pk2(qks[q], 0.f);
            bias[q][c] = add2(bias[q][c], p);
        }
    }
    // write partial logits (rb2_b folded into kh=0 partial only)
    float* gw_part = kh ? gw_p1 : gw_p0;
#pragma unroll
    for (int q = 0; q < 4; q++) {
        u64* wq = (u64*)(gw_part + (i0 + q) * NB * HH + j * HH);
        if (kh == 0) {
#pragma unroll
            for (int c = 0; c < 4; c++) {
                u64 bb = pk2(rb2_b[2 * c], rb2_b[2 * c + 1]);
                wq[c] = add2(bias[q][c], bb);
            }
        } else {
#pragma unroll
            for (int c = 0; c < 4; c++) wq[c] = bias[q][c];
        }
    }
}

// ---------------- attention 1b: combine partials + softmax -> gw_p0 -----------------
__global__ __launch_bounds__(256, 4) void softmax_kernel(float* __restrict__ gw_all,
                                                         const float* __restrict__ gw_b) {
    const int i = blockIdx.x;
    const int t = threadIdx.x;
    __shared__ float sw[NB * 9];   // padded [j][9] for conflict-free per-head access

    float4* gw4 = (float4*)(gw_all + i * NB * HH);
    const float4* gwb4 = (const float4*)(gw_b + i * NB * HH);
#pragma unroll
    for (int l = 0; l < 4; l++) {
        int idx = l * 256 + t;              // 1024 float4
        float4 v = gw4[idx];
        float4 vb = gwb4[idx];
        v.x += vb.x; v.y += vb.y; v.z += vb.z; v.w += vb.w;
        int jj = idx >> 1, half = (idx & 1) * 4;
        sw[jj * 9 + half + 0] = v.x;
        sw[jj * 9 + half + 1] = v.y;
        sw[jj * 9 + half + 2] = v.z;
        sw[jj * 9 + half + 3] = v.w;
    }
    __syncthreads();
    {
        int h = t >> 5, lane = t & 31;
        float m = -1e30f;
        for (int jj = lane; jj < NB; jj += 32) m = fmaxf(m, sw[jj * 9 + h]);
#pragma unroll
        for (int o = 16; o; o >>= 1) m = fmaxf(m, __shfl_xor_sync(0xffffffff, m, o));
        float s = 0.f;
        for (int jj = lane; jj < NB; jj += 32) {
            float e = __expf(sw[jj * 9 + h] - m);
            sw[jj * 9 + h] = e;
            s += e;
        }
#pragma unroll
        for (int o = 16; o; o >>= 1) s += __shfl_xor_sync(0xffffffff, s, o);
        float inv = 1.0f / s;
        for (int jj = lane; jj < NB; jj += 32) sw[jj * 9 + h] *= inv;
    }
    __syncthreads();
#pragma unroll
    for (int l = 0; l < 4; l++) {
        int idx = l * 256 + t;
        int jj = idx >> 1, half = (idx & 1) * 4;
        float4 v;
        v.x = sw[jj * 9 + half + 0];
        v.y = sw[jj * 9 + half + 1];
        v.z = sw[jj * 9 + half + 2];
        v.w = sw[jj * 9 + half + 3];
        gw4[idx] = v;
    }
}

// ---------------- attention 2a: partial T + c1, 4 queries, j-quarters ----------------
// grid (128 groups, 4 j-quarters), 256 threads; 128 j each.
__global__ __launch_bounds__(256, 3) void attn_ctx(
    const float* __restrict__ qkv, const float* __restrict__ Pv,
    const float* __restrict__ rv1_b, const float* __restrict__ gw_all,
    float* __restrict__ Tp, float* __restrict__ c1p) {
    const int g = blockIdx.x;
    const int jp = blockIdx.y;
    const int i0 = g * 4;
    const int jbase = jp * 128;
    const int t = threadIdx.x;

    __shared__ __align__(16) float sm_gw[4][128 * HH];  // staged weights, 16KB

    // stage softmax weights for this j-quarter (coalesced)
#pragma unroll
    for (int q = 0; q < 4; q++) {
        const float4* src = (const float4*)(gw_all + (i0 + q) * NB * HH + jbase * HH);
        float4* dst = (float4*)sm_gw[q];
        dst[t] = src[t];   // 256 float4 = 128 j * 8 h
    }
    __syncthreads();

    const int h = t >> 5;
    float c1[4] = {};
    float pvq[4];
    {
        float pvb = 0.5f * rv1_b[t];
#pragma unroll
        for (int q = 0; q < 4; q++) pvq[q] = Pv[(i0 + q) * DD + t] + pvb;
    }
    const float* Vp = qkv + 2 * DD + t + jbase * QKVD;
    const float* Pvp = Pv + t + jbase * DD;
    u64 T[4][4] = {};
#pragma unroll 2
    for (int jj = 0; jj < 128; jj++) {
        float pv = Pvp[jj * DD];
        float v = Vp[jj * QKVD];
#pragma unroll
        for (int q = 0; q < 4; q++) {
            float s = silu_h(pvq[q] - pv);
            u64 sp = pk2(s, s);
            const float* gwq = sm_gw[q] + jj * HH;
            ulonglong2 w0 = *(const ulonglong2*)gwq;
            ulonglong2 w1 = *(const ulonglong2*)(gwq + 4);
            T[q][0] = fma2(sp, w0.x, T[q][0]);
            T[q][1] = fma2(sp, w0.y, T[q][1]);
            T[q][2] = fma2(sp, w1.x, T[q][2]);
            T[q][3] = fma2(sp, w1.y, T[q][3]);
            c1[q] = fmaf(gwq[h], v, c1[q]);
        }
    }
    int b = g * 4 + jp;
#pragma unroll
    for (int q = 0; q < 4; q++) {
        float* Tg = Tp + (b * 4 + q) * (HH * DD);
#pragma unroll
        for (int c = 0; c < 4; c++) {
            float2 a = up2(T[q][c]);
            Tg[(2 * c) * DD + t] = a.x;
            Tg[(2 * c + 1) * DD + t] = a.y;
        }
        c1p[(b * 4 + q) * DD + t] = c1[q];
    }
}

// ---------------- attention 2b: combine + context2 + residual + fused LN2 -----------
// grid 128 groups; combines 4 j-quarters x 4 queries.
__global__ __launch_bounds__(256, 3) void attn_fin(
    const float* __restrict__ x, const float* __restrict__ rv2T,
    const float* __restrict__ rv2_b, const float* __restrict__ Tp,
    const float* __restrict__ c1p,
    const float* __restrict__ ln2_w, const float* __restrict__ ln2_b,
    float* __restrict__ y, float* __restrict__ xn2) {
    const int g = blockIdx.x;
    const int i0 = g * 4;
    const int t = threadIdx.x;

    __shared__ __align__(16) float sm_T[4][HH * DD];   // combined T, 32KB
    __shared__ float sred[8][8];

    // combine T quarters (coalesced float4)
#pragma unroll
    for (int q = 0; q < 4; q++) {
        float4* D = (float4*)sm_T[q];
#pragma unroll
        for (int l = 0; l < 2; l++) {
            int idx = l * 256 + t;   // 512 float4
            float4 acc = make_float4(0.f, 0.f, 0.f, 0.f);
#pragma unroll
            for (int jp = 0; jp < 4; jp++) {
                const float4* S = (const float4*)(Tp + ((g * 4 + jp) * 4 + q) * (HH * DD));
                float4 v = S[idx];
                acc.x += v.x; acc.y += v.y; acc.z += v.z; acc.w += v.w;
            }
            D[idx] = acc;
        }
    }
    __syncthreads();

    const int d = t;
    const int h = d >> 5;
    float c1[4] = {};
#pragma unroll
    for (int q = 0; q < 4; q++)
#pragma unroll
        for (int jp = 0; jp < 4; jp++)
            c1[q] += c1p[((g * 4 + jp) * 4 + q) * DD + d];

    float bv = rv2_b[d];
    float c2[4] = {bv, bv, bv, bv};
#pragma unroll 4
    for (int k = 0; k < DD; k++) {
        float rv = rv2T[k * DD + d];
        c2[0] += rv * sm_T[0][h * DD + k];
        c2[1] += rv * sm_T[1][h * DD + k];
        c2[2] += rv * sm_T[2][h * DD + k];
        c2[3] += rv * sm_T[3][h * DD + k];
    }
    float yv[4];
#pragma unroll
    for (int q = 0; q < 4; q++) {
        yv[q] = x[(i0 + q) * DD + d] + c1[q] + c2[q];
        y[(i0 + q) * DD + d] = yv[q];
    }

    // fused LN2 over 4 rows
    float s[4], qq[4];
#pragma unroll
    for (int q = 0; q < 4; q++) { s[q] = yv[q]; qq[q] = yv[q] * yv[q]; }
#pragma unroll
    for (int o = 16; o; o >>= 1)
#pragma unroll
        for (int q = 0; q < 4; q++) {
            s[q] += __shfl_xor_sync(0xffffffff, s[q], o);
            qq[q] += __shfl_xor_sync(0xffffffff, qq[q], o);
        }
    int warp = t >> 5, lane = t & 31;
    if (lane == 0)
#pragma unroll
        for (int q = 0; q < 4; q++) { sred[q][warp] = s[q]; sred[4 + q][warp] = qq[q]; }
    __syncthreads();
#pragma unroll
    for (int q = 0; q < 4; q++) {
        float S = 0.f, Q = 0.f;
#pragma unroll
        for (int k = 0; k < 8; k++) { S += sred[q][k]; Q += sred[4 + q][k]; }
        float m = S * (1.0f / DD);
        float var = Q * (1.0f / DD) - m * m;
        xn2[(i0 + q) * DD + d] = (yv[q] - m) * rsqrtf(var + 1e-5f) * ln2_w[d] + ln2_b[d];
    }
}

// ---------------- host launcher ----------------
extern "C" void kernel_launch(void* const* d_in, const int* in_sizes, int n_in,
                              void* d_out, int out_size) {
    const float* x      = (const float*)d_in[0];
    const float* coords = (const float*)d_in[1];
    const float* ln1_w  = (const float*)d_in[2];
    const float* ln1_b  = (const float*)d_in[3];
    const float* ln2_w  = (const float*)d_in[4];
    const float* ln2_b  = (const float*)d_in[5];
    const float* qkv_w  = (const float*)d_in[6];
    const float* qkv_b  = (const float*)d_in[7];
    const float* rb1_w  = (const float*)d_in[8];
    const float* rb1_b  = (const float*)d_in[9];
    const float* rb2_w  = (const float*)d_in[10];
    const float* rb2_b  = (const float*)d_in[11];
    const float* rv1_w  = (const float*)d_in[12];
    const float* rv1_b  = (const float*)d_in[13];
    const float* rv2_w  = (const float*)d_in[14];
    const float* rv2_b  = (const float*)d_in[15];
    const float* ffn_w1 = (const float*)d_in[16];
    const float* ffn_b1 = (const float*)d_in[17];
    const float* ffn_w2 = (const float*)d_in[18];
    const float* ffn_b2 = (const float*)d_in[19];
    const float* ffn_w3 = (const float*)d_in[20];
    const float* ffn_b3 = (const float*)d_in[21];
    float* out = (float*)d_out;

    float *p_xn, *p_qkv, *p_Pb, *p_Pv, *p_rv2T, *p_w, *p_w2, *p_Tp, *p_c1p, *p_y, *p_xn2, *p_h1;
    float2* p_PKT;
    cudaGetSymbolAddress((void**)&p_xn, g_xn);
    cudaGetSymbolAddress((void**)&p_qkv, g_qkv);
    cudaGetSymbolAddress((void**)&p_PKT, g_PKT);
    cudaGetSymbolAddress((void**)&p_Pb, g_Pb);
    cudaGetSymbolAddress((void**)&p_Pv, g_Pv);
    cudaGetSymbolAddress((void**)&p_rv2T, g_rv2T);
    cudaGetSymbolAddress((void**)&p_w, g_w);
    cudaGetSymbolAddress((void**)&p_w2, g_w2);
    cudaGetSymbolAddress((void**)&p_Tp, g_Tp);
    cudaGetSymbolAddress((void**)&p_c1p, g_c1p);
    cudaGetSymbolAddress((void**)&p_y, g_y);
    cudaGetSymbolAddress((void**)&p_xn2, g_xn2);
    cudaGetSymbolAddress((void**)&p_h1, g_h1);

    dim3 tthr(32, 8);

    // 1. LN1
    ln_kernel<<<NB, 256>>>(x, ln1_w, ln1_b, p_xn);
    // 2. QKV = xn @ qkv_w^T + qkv_b  (+ K^T side-write into PKT.x)
    gemm_t<<<dim3(QKVD / 64, NB / 32), 256>>>(p_xn, qkv_w, qkv_b, p_PKT, p_qkv,
                                              NB, QKVD, DD);
    // 3. coords projections (half-scaled: Pb, PKT.y, Pv)
    proj3_kernel<<<NB, 256>>>(coords, rb1_w, rv1_w, p_Pb, p_PKT, p_Pv);
    // 4. attention 1a: partial logits (4 queries x j-half x k-half, 512 blocks)
    attn_logits<<<dim3(NB / 4, 2, 2), 256>>>(p_qkv, p_PKT, p_Pb, rb1_b, rb2_w,
                                             rb2_b, p_w, p_w2);
    // 5. rv2^T
    transpose_kernel<<<dim3(DD / 32, DD / 32), tthr>>>(rv2_w, p_rv2T, DD, DD, DD, 0);
    // 6. attention 1b: combine partials + softmax in place
    softmax_kernel<<<NB, 256>>>(p_w, p_w2);
    // 7. attention 2a: partial T + c1 (4 queries x j-quarters, 512 blocks)
    attn_ctx<<<dim3(NB / 4, 4), 256>>>(p_qkv, p_Pv, rv1_b, p_w, p_Tp, p_c1p);
    // 8. attention 2b: combine + c2 + residual + fused LN2 (128 blocks)
    attn_fin<<<NB / 4, 256>>>(x, p_rv2T, rv2_b, p_Tp, p_c1p, ln2_w, ln2_b, p_y, p_xn2);
    // 9. fused SwiGLU dual-GEMM
    gemm_swiglu<<<dim3((HID + 63) / 64, NB / 32), 256>>>(p_xn2, ffn_w1, ffn_b1,
                                                         ffn_w2, ffn_b2, p_h1,
                                                         NB, HID, DD);
    // 10. out = h1 @ ffn_w3^T + ffn_b3 + y   (32x32 tiles -> 128 blocks)
    gemm_t32<<<dim3(DD / 32, NB / 32), 256>>>(p_h1, ffn_w3, ffn_b3, p_y, out,
                                              NB, DD, HID);
}

// round 17
// speedup vs baseline: 1.0261x; 1.0001x over previous
#include <cuda_runtime.h>
#include <cuda_bf16.h>

// Shapes (compile-time constants)
#define NB   512           // sequence length
#define DD   256           // model dim
#define HH   8             // heads
#define HID  682           // swiglu hidden
#define QKVD 768

typedef unsigned long long u64;

// ---------------- device scratch ----------------
__device__ float g_xn[NB * DD];
__device__ float g_qkv[NB * QKVD];
__device__ float2 g_PKT[DD * NB];    // (.x = K^T[k][j], .y = 0.5*Pb^T[k][j])
__device__ float g_Pb[NB * DD];      // 0.5 * Pb
__device__ float g_Pv[NB * DD];      // 0.5 * Pv
__device__ float g_rv2T[DD * DD];    // rv2 transposed [k][d]
__device__ float g_w[NB * NB * HH];  // logit partial kh=0 -> final softmax weights (8MB)
__device__ float g_w2[NB * NB * HH]; // logit partial kh=1 (8MB)
__device__ float g_Tp[512 * 4 * HH * DD];  // partial T: [(g*4+jp)*4+q][h*DD+k] (16MB)
__device__ float g_c1p[512 * 4 * DD];      // partial c1 (2MB)
__device__ float g_y[NB * DD];
__device__ float g_xn2[NB * DD];
__device__ float g_h1[NB * HID];

// ---- packed f32x2 helpers (sm_100+) ----
__device__ __forceinline__ u64 pk2(float lo, float hi) {
    u64 r;
    asm("mov.b64 %0, {%1, %2};" : "=l"(r) : "f"(lo), "f"(hi));
    return r;
}
__device__ __forceinline__ float2 up2(u64 v) {
    float2 f;
    asm("mov.b64 {%0, %1}, %2;" : "=f"(f.x), "=f"(f.y) : "l"(v));
    return f;
}
__device__ __forceinline__ u64 fma2(u64 a, u64 b, u64 c) {
    u64 d;
    asm("fma.rn.f32x2 %0, %1, %2, %3;" : "=l"(d) : "l"(a), "l"(b), "l"(c));
    return d;
}
__device__ __forceinline__ u64 add2(u64 a, u64 b) {
    u64 d;
    asm("add.rn.f32x2 %0, %1, %2;" : "=l"(d) : "l"(a), "l"(b));
    return d;
}

// silu from the HALF-difference s = 0.5*(a-b): silu(a-b) = s*tanh(s)+s
__device__ __forceinline__ float silu_h(float s) {
    float t;
    asm("tanh.approx.f32 %0, %1;" : "=f"(t) : "f"(s));
    return fmaf(s, t, s);
}
// accurate silu for the (cold) FFN epilogue
__device__ __forceinline__ float silu_acc(float v) {
    return v / (1.0f + __expf(-v));
}

// ---------------- LayerNorm: one block per row, 256 threads ----------------
__global__ __launch_bounds__(256) void ln_kernel(const float* __restrict__ x,
                                                 const float* __restrict__ w,
                                                 const float* __restrict__ b,
                                                 float* __restrict__ out) {
    int row = blockIdx.x, t = threadIdx.x;
    float v = x[row * DD + t];
    float s = v, q = v * v;
#pragma unroll
    for (int o = 16; o; o >>= 1) {
        s += __shfl_xor_sync(0xffffffff, s, o);
        q += __shfl_xor_sync(0xffffffff, q, o);
    }
    __shared__ float ss[8], sq[8];
    int warp = t >> 5, lane = t & 31;
    if (lane == 0) { ss[warp] = s; sq[warp] = q; }
    __syncthreads();
    s = 0.f; q = 0.f;
#pragma unroll
    for (int k = 0; k < 8; k++) { s += ss[k]; q += sq[k]; }
    float mean = s * (1.0f / DD);
    float var = q * (1.0f / DD) - mean * mean;
    out[row * DD + t] = (v - mean) * rsqrtf(var + 1e-5f) * w[t] + b[t];
}

// ---------------- coords projection (all outputs HALF-scaled) ----------------
__global__ __launch_bounds__(256) void proj3_kernel(const float* __restrict__ coords,
                                                    const float* __restrict__ rb1,
                                                    const float* __restrict__ rv1,
                                                    float* __restrict__ Pb,
                                                    float2* __restrict__ PKT,
                                                    float* __restrict__ Pv) {
    int i = blockIdx.x, k = threadIdx.x;
    float c0 = coords[i * 3 + 0], c1 = coords[i * 3 + 1], c2 = coords[i * 3 + 2];
    float pb = rb1[k * 3 + 0] * c0 + rb1[k * 3 + 1] * c1 + rb1[k * 3 + 2] * c2;
    float pv = rv1[k * 3 + 0] * c0 + rv1[k * 3 + 1] * c1 + rv1[k * 3 + 2] * c2;
    Pb[i * DD + k] = 0.5f * pb;
    PKT[k * NB + i].y = 0.5f * pb;
    Pv[i * DD + k] = 0.5f * pv;
}

// ---------------- generic 32x32-tiled transpose ----------------
__global__ __launch_bounds__(256) void transpose_kernel(const float* __restrict__ in,
                                                        float* __restrict__ out,
                                                        int R, int C, int ldin, int off) {
    __shared__ float tile[32][33];
    int c0 = blockIdx.x * 32, r0 = blockIdx.y * 32;
    int tx = threadIdx.x, ty = threadIdx.y;  // 32 x 8
#pragma unroll
    for (int s = 0; s < 32; s += 8)
        tile[ty + s][tx] = in[(r0 + ty + s) * ldin + off + c0 + tx];
    __syncthreads();
#pragma unroll
    for (int s = 0; s < 32; s += 8)
        out[(c0 + ty + s) * R + r0 + tx] = tile[tx][ty + s];
}

// ---------------- GEMM: C = A @ W^T (+bias), 32x64 tile; optional K^T side-write ----
__global__ __launch_bounds__(256, 2) void gemm_t(const float* __restrict__ A,
                                                 const float* __restrict__ W,
                                                 const float* __restrict__ bias,
                                                 float2* __restrict__ PKT,  // nullable
                                                 float* __restrict__ C,
                                                 int M, int N, int K) {
    __shared__ __align__(16) u64 As[32][34];     // [k][m] duplicated
    __shared__ __align__(16) float Ws[32][68];   // [k][n]
    int tid = threadIdx.x;
    int tx = tid & 15, ty = tid >> 4;            // tx -> n (4 cols), ty -> m (2 rows)
    int row0 = blockIdx.y * 32, col0 = blockIdx.x * 64;
    u64 acc[2][2] = {};
    for (int k0 = 0; k0 < K; k0 += 32) {
#pragma unroll
        for (int l = 0; l < 4; l++) {            // A: 32x32
            int idx = l * 256 + tid;
            int m = idx >> 5, k = idx & 31;
            int gk = k0 + k, ar = row0 + m;
            float v = (ar < M && gk < K) ? A[ar * K + gk] : 0.f;
            As[k][m] = pk2(v, v);
        }
#pragma unroll
        for (int l = 0; l < 8; l++) {            // W: 64x32
            int idx = l * 256 + tid;
            int m = idx >> 5, k = idx & 31;
            int gk = k0 + k, wr = col0 + m;
            Ws[k][m] = (wr < N && gk < K) ? W[wr * K + gk] : 0.f;
        }
        __syncthreads();
#pragma unroll
        for (int kk = 0; kk < 32; kk++) {
            ulonglong2 Av = *(const ulonglong2*)&As[kk][ty * 2];
            ulonglong2 Bv = *(const ulonglong2*)&Ws[kk][tx * 4];
            acc[0][0] = fma2(Av.x, Bv.x, acc[0][0]);
            acc[0][1] = fma2(Av.x, Bv.y, acc[0][1]);
            acc[1][0] = fma2(Av.y, Bv.x, acc[1][0]);
            acc[1][1] = fma2(Av.y, Bv.y, acc[1][1]);
        }
        __syncthreads();
    }
#pragma unroll
    for (int r = 0; r < 2; r++) {
        int m = row0 + ty * 2 + r;
        if (m >= M) continue;
#pragma unroll
        for (int c2 = 0; c2 < 2; c2++) {
            float2 v = up2(acc[r][c2]);
            int n0 = col0 + tx * 4 + c2 * 2;
            if (n0 < N) {
                float o = v.x + (bias ? bias[n0] : 0.f);
                C[m * N + n0] = o;
                if (PKT && n0 >= DD && n0 < 2 * DD) PKT[(n0 - DD) * NB + m].x = o;
            }
            if (n0 + 1 < N) {
                float o = v.y + (bias ? bias[n0 + 1] : 0.f);
                C[m * N + n0 + 1] = o;
                if (PKT && n0 + 1 >= DD && n0 + 1 < 2 * DD) PKT[(n0 + 1 - DD) * NB + m].x = o;
            }
        }
    }
}

// ---------------- GEMM 32x32 tile (better grid fill for small N) ----------------
__global__ __launch_bounds__(256, 3) void gemm_t32(const float* __restrict__ A,
                                                   const float* __restrict__ W,
                                                   const float* __restrict__ bias,
                                                   const float* __restrict__ residual,
                                                   float* __restrict__ C,
                                                   int M, int N, int K) {
    __shared__ __align__(16) u64 As[32][34];     // [k][m] duplicated
    __shared__ __align__(16) float Ws[32][36];   // [k][n]
    int tid = threadIdx.x;
    int tx = tid & 7, ty = tid >> 3;             // tx -> n (4 cols), ty -> m (1 row)
    int row0 = blockIdx.y * 32, col0 = blockIdx.x * 32;
    u64 acc[2] = {};
    for (int k0 = 0; k0 < K; k0 += 32) {
#pragma unroll
        for (int l = 0; l < 4; l++) {
            int idx = l * 256 + tid;
            int m = idx >> 5, k = idx & 31;
            int gk = k0 + k;
            int ar = row0 + m, wr = col0 + m;
            float va = (ar < M && gk < K) ? A[ar * K + gk] : 0.f;
            As[k][m] = pk2(va, va);
            Ws[k][m] = (wr < N && gk < K) ? W[wr * K + gk] : 0.f;
        }
        __syncthreads();
#pragma unroll
        for (int kk = 0; kk < 32; kk++) {
            u64 Av = As[kk][ty];
            ulonglong2 Bv = *(const ulonglong2*)&Ws[kk][tx * 4];
            acc[0] = fma2(Av, Bv.x, acc[0]);
            acc[1] = fma2(Av, Bv.y, acc[1]);
        }
        __syncthreads();
    }
    int m = row0 + ty;
    if (m < M) {
#pragma unroll
        for (int c2 = 0; c2 < 2; c2++) {
            float2 v = up2(acc[c2]);
            int n0 = col0 + tx * 4 + c2 * 2;
            if (n0 < N) {
                float o = v.x;
                if (bias) o += bias[n0];
                if (residual) o += residual[m * N + n0];
                C[m * N + n0] = o;
            }
            if (n0 + 1 < N) {
                float o = v.y;
                if (bias) o += bias[n0 + 1];
                if (residual) o += residual[m * N + n0 + 1];
                C[m * N + n0 + 1] = o;
            }
        }
    }
}

// ---------------- fused SwiGLU dual-GEMM, 32x64 tile ----------------
__global__ __launch_bounds__(256, 2) void gemm_swiglu(const float* __restrict__ A,
                                                      const float* __restrict__ W1,
                                                      const float* __restrict__ b1,
                                                      const float* __restrict__ W2,
                                                      const float* __restrict__ b2,
                                                      float* __restrict__ Hout,
                                                      int M, int N, int K) {
    __shared__ __align__(16) u64 As[32][34];
    __shared__ __align__(16) float W1s[32][68];
    __shared__ __align__(16) float W2s[32][68];
    int tid = threadIdx.x;
    int tx = tid & 15, ty = tid >> 4;
    int row0 = blockIdx.y * 32, col0 = blockIdx.x * 64;
    u64 acc1[2][2] = {};
    u64 acc2[2][2] = {};
    for (int k0 = 0; k0 < K; k0 += 32) {
#pragma unroll
        for (int l = 0; l < 4; l++) {
            int idx = l * 256 + tid;
            int m = idx >> 5, k = idx & 31;
            int gk = k0 + k, ar = row0 + m;
            float v = (ar < M && gk < K) ? A[ar * K + gk] : 0.f;
            As[k][m] = pk2(v, v);
        }
#pragma unroll
        for (int l = 0; l < 8; l++) {
            int idx = l * 256 + tid;
            int m = idx >> 5, k = idx & 31;
            int gk = k0 + k, wr = col0 + m;
            W1s[k][m] = (wr < N && gk < K) ? W1[wr * K + gk] : 0.f;
            W2s[k][m] = (wr < N && gk < K) ? W2[wr * K + gk] : 0.f;
        }
        __syncthreads();
#pragma unroll
        for (int kk = 0; kk < 32; kk++) {
            ulonglong2 Av = *(const ulonglong2*)&As[kk][ty * 2];
            ulonglong2 Bv = *(const ulonglong2*)&W1s[kk][tx * 4];
            ulonglong2 Cv = *(const ulonglong2*)&W2s[kk][tx * 4];
            acc1[0][0] = fma2(Av.x, Bv.x, acc1[0][0]);
            acc1[0][1] = fma2(Av.x, Bv.y, acc1[0][1]);
            acc1[1][0] = fma2(Av.y, Bv.x, acc1[1][0]);
            acc1[1][1] = fma2(Av.y, Bv.y, acc1[1][1]);
            acc2[0][0] = fma2(Av.x, Cv.x, acc2[0][0]);
            acc2[0][1] = fma2(Av.x, Cv.y, acc2[0][1]);
            acc2[1][0] = fma2(Av.y, Cv.x, acc2[1][0]);
            acc2[1][1] = fma2(Av.y, Cv.y, acc2[1][1]);
        }
        __syncthreads();
    }
#pragma unroll
    for (int r = 0; r < 2; r++) {
        int m = row0 + ty * 2 + r;
        if (m >= M) continue;
#pragma unroll
        for (int c2 = 0; c2 < 2; c2++) {
            float2 v1 = up2(acc1[r][c2]);
            float2 v2 = up2(acc2[r][c2]);
            int n0 = col0 + tx * 4 + c2 * 2;
            if (n0 < N)
                Hout[m * N + n0] = silu_acc(v1.x + b1[n0]) * (v2.x + b2[n0]);
            if (n0 + 1 < N)
                Hout[m * N + n0 + 1] = silu_acc(v1.y + b1[n0 + 1]) * (v2.y + b2[n0 + 1]);
        }
    }
}

// ---------------- attention 1a: partial logits, 4 queries per block -----------------
// grid (128 groups, 2 j-halves, 2 k-halves), 256 threads; thread owns one j, 4 queries.
__global__ __launch_bounds__(256, 3) void attn_logits(
    const float* __restrict__ qkv, const float2* __restrict__ PKT,
    const float* __restrict__ Pb, const float* __restrict__ rb1_b,
    const float* __restrict__ rb2_w, const float* __restrict__ rb2_b,
    float* __restrict__ gw_p0, float* __restrict__ gw_p1) {
    const int i0 = blockIdx.x * 4;
    const int j = blockIdx.y * 256 + threadIdx.x;
    const int kh = blockIdx.z;
    const int kbase = kh * 128;
    const int t = threadIdx.x;

    __shared__ __align__(16) float4 sm_q[128];        // q for 4 queries, k-half
    __shared__ __align__(16) float4 sm_hpb[128];      // 0.5*Pbq for 4 queries
    __shared__ __align__(16) float sm_rb2[128 * HH];  // rb2 transposed [k'][h]

    if (t < 128) {
        int k = kbase + t;
        float hb = 0.5f * rb1_b[k];
        sm_q[t] = make_float4(qkv[(i0 + 0) * QKVD + k], qkv[(i0 + 1) * QKVD + k],
                              qkv[(i0 + 2) * QKVD + k], qkv[(i0 + 3) * QKVD + k]);
        sm_hpb[t] = make_float4(Pb[(i0 + 0) * DD + k] + hb, Pb[(i0 + 1) * DD + k] + hb,
                                Pb[(i0 + 2) * DD + k] + hb, Pb[(i0 + 3) * DD + k] + hb);
    }
#pragma unroll
    for (int l = 0; l < 4; l++) {
        int idx = l * 256 + t;          // 0..1023
        int h = idx >> 7, kp = idx & 127;
        sm_rb2[kp * HH + h] = rb2_w[h * DD + kbase + kp];
    }
    __syncthreads();

    u64 bias[4][4] = {};   // [q][head pair], partial over this k-half
    const float sc = 0.17677669529663687f;
#pragma unroll
    for (int hq = 0; hq < 4; hq++) {     // global head = kh*4+hq
        float qk0 = 0.f, qk1 = 0.f, qk2 = 0.f, qk3 = 0.f;
#pragma unroll 4
        for (int kk = 0; kk < 32; kk++) {
            int kp = hq * 32 + kk;
            float2 pk = PKT[(kbase + kp) * NB + j];
            ulonglong2 rA = *(const ulonglong2*)(sm_rb2 + kp * HH);
            ulonglong2 rB = *(const ulonglong2*)(sm_rb2 + kp * HH + 4);
            float4 qv = sm_q[kp];
            float4 hp = sm_hpb[kp];
            qk0 = fmaf(qv.x, pk.x, qk0);
            qk1 = fmaf(qv.y, pk.x, qk1);
            qk2 = fmaf(qv.z, pk.x, qk2);
            qk3 = fmaf(qv.w, pk.x, qk3);
            {
                float u = silu_h(hp.x - pk.y);
                u64 up = pk2(u, u);
                bias[0][0] = fma2(up, rA.x, bias[0][0]);
                bias[0][1] = fma2(up, rA.y, bias[0][1]);
                bias[0][2] = fma2(up, rB.x, bias[0][2]);
                bias[0][3] = fma2(up, rB.y, bias[0][3]);
            }
            {
                float u = silu_h(hp.y - pk.y);
                u64 up = pk2(u, u);
                bias[1][0] = fma2(up, rA.x, bias[1][0]);
                bias[1][1] = fma2(up, rA.y, bias[1][1]);
                bias[1][2] = fma2(up, rB.x, bias[1][2]);
                bias[1][3] = fma2(up, rB.y, bias[1][3]);
            }
            {
                float u = silu_h(hp.z - pk.y);
                u64 up = pk2(u, u);
                bias[2][0] = fma2(up, rA.x, bias[2][0]);
                bias[2][1] = fma2(up, rA.y, bias[2][1]);
                bias[2][2] = fma2(up, rB.x, bias[2][2]);
                bias[2][3] = fma2(up, rB.y, bias[2][3]);
            }
            {
                float u = silu_h(hp.w - pk.y);
                u64 up = pk2(u, u);
                bias[3][0] = fma2(up, rA.x, bias[3][0]);
                bias[3][1] = fma2(up, rA.y, bias[3][1]);
                bias[3][2] = fma2(up, rB.x, bias[3][2]);
                bias[3][3] = fma2(up, rB.y, bias[3][3]);
            }
        }
        int hg = kh * 4 + hq;
        int c = hg >> 1;
        float qks[4] = {qk0 * sc, qk1 * sc, qk2 * sc, qk3 * sc};
#pragma unroll
        for (int q = 0; q < 4; q++) {
            u64 p = (hg & 1) ? pk2(0.f, qks[q]) : pk2(qks[q], 0.f);
            bias[q][c] = add2(bias[q][c], p);
        }
    }
    // write partial logits (rb2_b folded into kh=0 partial only)
    float* gw_part = kh ? gw_p1 : gw_p0;
#pragma unroll
    for (int q = 0; q < 4; q++) {
        u64* wq = (u64*)(gw_part + (i0 + q) * NB * HH + j * HH);
        if (kh == 0) {
#pragma unroll
            for (int c = 0; c < 4; c++) {
                u64 bb = pk2(rb2_b[2 * c], rb2_b[2 * c + 1]);
                wq[c] = add2(bias[q][c], bb);
            }
        } else {
#pragma unroll
            for (int c = 0; c < 4; c++) wq[c] = bias[q][c];
        }
    }
}

// ---------------- attention 1b: combine partials + softmax -> gw_p0 -----------------
__global__ __launch_bounds__(256, 4) void softmax_kernel(float* __restrict__ gw_all,
                                                         const float* __restrict__ gw_b) {
    const int i = blockIdx.x;
    const int t = threadIdx.x;
    __shared__ float sw[NB * 9];   // padded [j][9] for conflict-free per-head access

    float4* gw4 = (float4*)(gw_all + i * NB * HH);
    const float4* gwb4 = (const float4*)(gw_b + i * NB * HH);
#pragma unroll
    for (int l = 0; l < 4; l++) {
        int idx = l * 256 + t;              // 1024 float4
        float4 v = gw4[idx];
        float4 vb = gwb4[idx];
        v.x += vb.x; v.y += vb.y; v.z += vb.z; v.w += vb.w;
        int jj = idx >> 1, half = (idx & 1) * 4;
        sw[jj * 9 + half + 0] = v.x;
        sw[jj * 9 + half + 1] = v.y;
        sw[jj * 9 + half + 2] = v.z;
        sw[jj * 9 + half + 3] = v.w;
    }
    __syncthreads();
    {
        int h = t >> 5, lane = t & 31;
        float m = -1e30f;
        for (int jj = lane; jj < NB; jj += 32) m = fmaxf(m, sw[jj * 9 + h]);
#pragma unroll
        for (int o = 16; o; o >>= 1) m = fmaxf(m, __shfl_xor_sync(0xffffffff, m, o));
        float s = 0.f;
        for (int jj = lane; jj < NB; jj += 32) {
            float e = __expf(sw[jj * 9 + h] - m);
            sw[jj * 9 + h] = e;
            s += e;
        }
#pragma unroll
        for (int o = 16; o; o >>= 1) s += __shfl_xor_sync(0xffffffff, s, o);
        float inv = 1.0f / s;
        for (int jj = lane; jj < NB; jj += 32) sw[jj * 9 + h] *= inv;
    }
    __syncthreads();
#pragma unroll
    for (int l = 0; l < 4; l++) {
        int idx = l * 256 + t;
        int jj = idx >> 1, half = (idx & 1) * 4;
        float4 v;
        v.x = sw[jj * 9 + half + 0];
        v.y = sw[jj * 9 + half + 1];
        v.z = sw[jj * 9 + half + 2];
        v.w = sw[jj * 9 + half + 3];
        gw4[idx] = v;
    }
}

// ---------------- attention 2a: partial T + c1, 4 queries, j-quarters ----------------
// grid (128 groups, 4 j-quarters), 256 threads; 128 j each.
__global__ __launch_bounds__(256, 3) void attn_ctx(
    const float* __restrict__ qkv, const float* __restrict__ Pv,
    const float* __restrict__ rv1_b, const float* __restrict__ gw_all,
    float* __restrict__ Tp, float* __restrict__ c1p) {
    const int g = blockIdx.x;
    const int jp = blockIdx.y;
    const int i0 = g * 4;
    const int jbase = jp * 128;
    const int t = threadIdx.x;

    __shared__ __align__(16) float sm_gw[4][128 * HH];  // staged weights, 16KB

    // stage softmax weights for this j-quarter (coalesced)
#pragma unroll
    for (int q = 0; q < 4; q++) {
        const float4* src = (const float4*)(gw_all + (i0 + q) * NB * HH + jbase * HH);
        float4* dst = (float4*)sm_gw[q];
        dst[t] = src[t];   // 256 float4 = 128 j * 8 h
    }
    __syncthreads();

    const int h = t >> 5;
    float c1[4] = {};
    float pvq[4];
    {
        float pvb = 0.5f * rv1_b[t];
#pragma unroll
        for (int q = 0; q < 4; q++) pvq[q] = Pv[(i0 + q) * DD + t] + pvb;
    }
    const float* Vp = qkv + 2 * DD + t + jbase * QKVD;
    const float* Pvp = Pv + t + jbase * DD;
    u64 T[4][4] = {};
#pragma unroll 2
    for (int jj = 0; jj < 128; jj++) {
        float pv = Pvp[jj * DD];
        float v = Vp[jj * QKVD];
#pragma unroll
        for (int q = 0; q < 4; q++) {
            float s = silu_h(pvq[q] - pv);
            u64 sp = pk2(s, s);
            const float* gwq = sm_gw[q] + jj * HH;
            ulonglong2 w0 = *(const ulonglong2*)gwq;
            ulonglong2 w1 = *(const ulonglong2*)(gwq + 4);
            T[q][0] = fma2(sp, w0.x, T[q][0]);
            T[q][1] = fma2(sp, w0.y, T[q][1]);
            T[q][2] = fma2(sp, w1.x, T[q][2]);
            T[q][3] = fma2(sp, w1.y, T[q][3]);
            c1[q] = fmaf(gwq[h], v, c1[q]);
        }
    }
    int b = g * 4 + jp;
#pragma unroll
    for (int q = 0; q < 4; q++) {
        float* Tg = Tp + (b * 4 + q) * (HH * DD);
#pragma unroll
        for (int c = 0; c < 4; c++) {
            float2 a = up2(T[q][c]);
            Tg[(2 * c) * DD + t] = a.x;
            Tg[(2 * c + 1) * DD + t] = a.y;
        }
        c1p[(b * 4 + q) * DD + t] = c1[q];
    }
}

// ---------------- attention 2b: combine + context2 + residual + fused LN2 -----------
// grid 128 groups; combines 4 j-quarters x 4 queries.
__global__ __launch_bounds__(256, 3) void attn_fin(
    const float* __restrict__ x, const float* __restrict__ rv2T,
    const float* __restrict__ rv2_b, const float* __restrict__ Tp,
    const float* __restrict__ c1p,
    const float* __restrict__ ln2_w, const float* __restrict__ ln2_b,
    float* __restrict__ y, float* __restrict__ xn2) {
    const int g = blockIdx.x;
    const int i0 = g * 4;
    const int t = threadIdx.x;

    __shared__ __align__(16) float sm_T[4][HH * DD];   // combined T, 32KB
    __shared__ float sred[8][8];

    // combine T quarters (coalesced float4)
#pragma unroll
    for (int q = 0; q < 4; q++) {
        float4* D = (float4*)sm_T[q];
#pragma unroll
        for (int l = 0; l < 2; l++) {
            int idx = l * 256 + t;   // 512 float4
            float4 acc = make_float4(0.f, 0.f, 0.f, 0.f);
#pragma unroll
            for (int jp = 0; jp < 4; jp++) {
                const float4* S = (const float4*)(Tp + ((g * 4 + jp) * 4 + q) * (HH * DD));
                float4 v = S[idx];
                acc.x += v.x; acc.y += v.y; acc.z += v.z; acc.w += v.w;
            }
            D[idx] = acc;
        }
    }
    __syncthreads();

    const int d = t;
    const int h = d >> 5;
    float c1[4] = {};
#pragma unroll
    for (int q = 0; q < 4; q++)
#pragma unroll
        for (int jp = 0; jp < 4; jp++)
            c1[q] += c1p[((g * 4 + jp) * 4 + q) * DD + d];

    float bv = rv2_b[d];
    float c2[4] = {bv, bv, bv, bv};
#pragma unroll 4
    for (int k = 0; k < DD; k++) {
        float rv = rv2T[k * DD + d];
        c2[0] += rv * sm_T[0][h * DD + k];
        c2[1] += rv * sm_T[1][h * DD + k];
        c2[2] += rv * sm_T[2][h * DD + k];
        c2[3] += rv * sm_T[3][h * DD + k];
    }
    float yv[4];
#pragma unroll
    for (int q = 0; q < 4; q++) {
        yv[q] = x[(i0 + q) * DD + d] + c1[q] + c2[q];
        y[(i0 + q) * DD + d] = yv[q];
    }

    // fused LN2 over 4 rows
    float s[4], qq[4];
#pragma unroll
    for (int q = 0; q < 4; q++) { s[q] = yv[q]; qq[q] = yv[q] * yv[q]; }
#pragma unroll
    for (int o = 16; o; o >>= 1)
#pragma unroll
        for (int q = 0; q < 4; q++) {
            s[q] += __shfl_xor_sync(0xffffffff, s[q], o);
            qq[q] += __shfl_xor_sync(0xffffffff, qq[q], o);
        }
    int warp = t >> 5, lane = t & 31;
    if (lane == 0)
#pragma unroll
        for (int q = 0; q < 4; q++) { sred[q][warp] = s[q]; sred[4 + q][warp] = qq[q]; }
    __syncthreads();
#pragma unroll
    for (int q = 0; q < 4; q++) {
        float S = 0.f, Q = 0.f;
#pragma unroll
        for (int k = 0; k < 8; k++) { S += sred[q][k]; Q += sred[4 + q][k]; }
        float m = S * (1.0f / DD);
        float var = Q * (1.0f / DD) - m * m;
        xn2[(i0 + q) * DD + d] = (yv[q] - m) * rsqrtf(var + 1e-5f) * ln2_w[d] + ln2_b[d];
    }
}

// ---------------- host launcher ----------------
extern "C" void kernel_launch(void* const* d_in, const int* in_sizes, int n_in,
                              void* d_out, int out_size) {
    const float* x      = (const float*)d_in[0];
    const float* coords = (const float*)d_in[1];
    const float* ln1_w  = (const float*)d_in[2];
    const float* ln1_b  = (const float*)d_in[3];
    const float* ln2_w  = (const float*)d_in[4];
    const float* ln2_b  = (const float*)d_in[5];
    const float* qkv_w  = (const float*)d_in[6];
    const float* qkv_b  = (const float*)d_in[7];
    const float* rb1_w  = (const float*)d_in[8];
    const float* rb1_b  = (const float*)d_in[9];
    const float* rb2_w  = (const float*)d_in[10];
    const float* rb2_b  = (const float*)d_in[11];
    const float* rv1_w  = (const float*)d_in[12];
    const float* rv1_b  = (const float*)d_in[13];
    const float* rv2_w  = (const float*)d_in[14];
    const float* rv2_b  = (const float*)d_in[15];
    const float* ffn_w1 = (const float*)d_in[16];
    const float* ffn_b1 = (const float*)d_in[17];
    const float* ffn_w2 = (const float*)d_in[18];
    const float* ffn_b2 = (const float*)d_in[19];
    const float* ffn_w3 = (const float*)d_in[20];
    const float* ffn_b3 = (const float*)d_in[21];
    float* out = (float*)d_out;

    float *p_xn, *p_qkv, *p_Pb, *p_Pv, *p_rv2T, *p_w, *p_w2, *p_Tp, *p_c1p, *p_y, *p_xn2, *p_h1;
    float2* p_PKT;
    cudaGetSymbolAddress((void**)&p_xn, g_xn);
    cudaGetSymbolAddress((void**)&p_qkv, g_qkv);
    cudaGetSymbolAddress((void**)&p_PKT, g_PKT);
    cudaGetSymbolAddress((void**)&p_Pb, g_Pb);
    cudaGetSymbolAddress((void**)&p_Pv, g_Pv);
    cudaGetSymbolAddress((void**)&p_rv2T, g_rv2T);
    cudaGetSymbolAddress((void**)&p_w, g_w);
    cudaGetSymbolAddress((void**)&p_w2, g_w2);
    cudaGetSymbolAddress((void**)&p_Tp, g_Tp);
    cudaGetSymbolAddress((void**)&p_c1p, g_c1p);
    cudaGetSymbolAddress((void**)&p_y, g_y);
    cudaGetSymbolAddress((void**)&p_xn2, g_xn2);
    cudaGetSymbolAddress((void**)&p_h1, g_h1);

    dim3 tthr(32, 8);

    // 1. LN1
    ln_kernel<<<NB, 256>>>(x, ln1_w, ln1_b, p_xn);
    // 2. QKV = xn @ qkv_w^T + qkv_b  (+ K^T side-write into PKT.x)
    gemm_t<<<dim3(QKVD / 64, NB / 32), 256>>>(p_xn, qkv_w, qkv_b, p_PKT, p_qkv,
                                              NB, QKVD, DD);
    // 3. coords projections (half-scaled: Pb, PKT.y, Pv)
    proj3_kernel<<<NB, 256>>>(coords, rb1_w, rv1_w, p_Pb, p_PKT, p_Pv);
    // 4. attention 1a: partial logits (4 queries x j-half x k-half, 512 blocks)
    attn_logits<<<dim3(NB / 4, 2, 2), 256>>>(p_qkv, p_PKT, p_Pb, rb1_b, rb2_w,
                                             rb2_b, p_w, p_w2);
    // 5. rv2^T
    transpose_kernel<<<dim3(DD / 32, DD / 32), tthr>>>(rv2_w, p_rv2T, DD, DD, DD, 0);
    // 6. attention 1b: combine partials + softmax in place
    softmax_kernel<<<NB, 256>>>(p_w, p_w2);
    // 7. attention 2a: partial T + c1 (4 queries x j-quarters, 512 blocks)
    attn_ctx<<<dim3(NB / 4, 4), 256>>>(p_qkv, p_Pv, rv1_b, p_w, p_Tp, p_c1p);
    // 8. attention 2b: combine + c2 + residual + fused LN2 (128 blocks)
    attn_fin<<<NB / 4, 256>>>(x, p_rv2T, rv2_b, p_Tp, p_c1p, ln2_w, ln2_b, p_y, p_xn2);
    // 9. fused SwiGLU dual-GEMM
    gemm_swiglu<<<dim3((HID + 63) / 64, NB / 32), 256>>>(p_xn2, ffn_w1, ffn_b1,
                                                         ffn_w2, ffn_b2, p_h1,
                                                         NB, HID, DD);
    // 10. out = h1 @ ffn_w3^T + ffn_b3 + y   (32x32 tiles -> 128 blocks)
    gemm_t32<<<dim3(DD / 32, NB / 32), 256>>>(p_h1, ffn_w3, ffn_b3, p_y, out,
                                              NB, DD, HID);
}